// round 3
// baseline (speedup 1.0000x reference)
#include <cuda_runtime.h>
#include <math.h>

#define B_   16
#define N_   512
#define D_   768
#define H_   12
#define DK_  64
#define ND_  32
#define ROWS (B_*N_)            // 8192
#define OUT_OFF ((size_t)B_*N_*D_)  // 6291456

// ---------------- scratch (static device globals; no allocation) -------------
__device__ float g_x[ROWS*D_];
__device__ float g_q[ROWS*D_];
__device__ float g_k[ROWS*D_];
__device__ float g_v[ROWS*D_];
__device__ float g_ctx[ROWS*D_];
__device__ float g_px[ROWS];
__device__ float g_py[ROWS];

// ---------------- LayerNorm: one block per row (768 = 256*3) -----------------
__global__ void ln_kernel(const float* __restrict__ f,
                          const float* __restrict__ gamma,
                          const float* __restrict__ beta) {
    int row = blockIdx.x;
    int t = threadIdx.x;
    const float* fr = f + (size_t)row * D_;
    float v0 = fr[t], v1 = fr[t + 256], v2 = fr[t + 512];
    __shared__ float red[256];
    red[t] = v0 + v1 + v2;
    __syncthreads();
    for (int off = 128; off > 0; off >>= 1) {
        if (t < off) red[t] += red[t + off];
        __syncthreads();
    }
    float mu = red[0] * (1.0f / D_);
    __syncthreads();
    float d0 = v0 - mu, d1 = v1 - mu, d2 = v2 - mu;
    red[t] = d0 * d0 + d1 * d1 + d2 * d2;
    __syncthreads();
    for (int off = 128; off > 0; off >>= 1) {
        if (t < off) red[t] += red[t + off];
        __syncthreads();
    }
    float rstd = rsqrtf(red[0] * (1.0f / D_) + 1e-5f);
    float* xr = g_x + (size_t)row * D_;
    xr[t]       = d0 * rstd * gamma[t]       + beta[t];
    xr[t + 256] = d1 * rstd * gamma[t + 256] + beta[t + 256];
    xr[t + 512] = d2 * rstd * gamma[t + 512] + beta[t + 512];
}

// ---------------- patch bins (px, py) per (b, n) -----------------------------
__global__ void patch_kernel(const float* __restrict__ boxes,
                             const int* __restrict__ image_sizes) {
    int i = blockIdx.x * blockDim.x + threadIdx.x;
    if (i >= ROWS) return;
    int b = i / N_;
    float w = (float)image_sizes[b * 4 + 0];
    float h = (float)image_sizes[b * 4 + 1];
    const float* bx = boxes + (size_t)i * 4;
    float x0 = bx[0] * w, y0 = bx[1] * h, x1 = bx[2] * w, y1 = bx[3] * h;
    float spw = floorf(w / 11.0f);
    float sph = floorf(h / 11.0f);
    float cx = floorf((x0 + x1) / 2.0f);
    float cy = floorf((y0 + y1) / 2.0f);
    float px = 0.0f, py = 0.0f;
    #pragma unroll
    for (int j = 10; j >= 0; j--) {  // reverse scan; last hit = first match
        float lo = (float)j * spw, hi = (float)(j + 1) * spw;
        if (lo <= cx && cx <= hi) px = (float)j;
    }
    // reverse loop picks SMALLEST matching j only if we overwrite downward:
    // fix: scan forward, keep first
    px = 0.0f;
    for (int j = 0; j < 11; j++) {
        float lo = (float)j * spw, hi = (float)(j + 1) * spw;
        if (lo <= cx && cx <= hi) { px = (float)j; break; }
    }
    for (int j = 0; j < 11; j++) {
        float lo = (float)j * sph, hi = (float)(j + 1) * sph;
        if (lo <= cy && cy <= hi) { py = (float)j; break; }
    }
    g_px[i] = px;
    g_py[i] = py;
}

// ---------------- SGEMM: C[M,N] = A[M,K] @ W[N,K]^T + bias -------------------
// 128x128 tile, BK=8, 256 threads, 8x8 per thread.
__global__ void __launch_bounds__(256) gemm_bias(
        const float* __restrict__ A, const float* __restrict__ W,
        const float* __restrict__ bias, float* __restrict__ C,
        int M, int N, int K) {
    __shared__ float As[8][128];
    __shared__ float Bs[8][128];
    int tid = threadIdx.x;
    int tx = tid & 15, ty = tid >> 4;
    int m0 = blockIdx.y * 128, n0 = blockIdx.x * 128;
    int lr = tid >> 1;
    int lc = (tid & 1) << 2;
    const float* Ab = A + (size_t)(m0 + lr) * K + lc;
    const float* Wb = W + (size_t)(n0 + lr) * K + lc;
    float acc[8][8];
    #pragma unroll
    for (int i = 0; i < 8; i++)
        #pragma unroll
        for (int j = 0; j < 8; j++) acc[i][j] = 0.0f;

    for (int k0 = 0; k0 < K; k0 += 8) {
        float4 a4 = *(const float4*)(Ab + k0);
        float4 b4 = *(const float4*)(Wb + k0);
        As[lc + 0][lr] = a4.x; As[lc + 1][lr] = a4.y;
        As[lc + 2][lr] = a4.z; As[lc + 3][lr] = a4.w;
        Bs[lc + 0][lr] = b4.x; Bs[lc + 1][lr] = b4.y;
        Bs[lc + 2][lr] = b4.z; Bs[lc + 3][lr] = b4.w;
        __syncthreads();
        #pragma unroll
        for (int kk = 0; kk < 8; kk++) {
            float ar[8], br[8];
            *(float4*)(ar)     = *(const float4*)&As[kk][ty * 8];
            *(float4*)(ar + 4) = *(const float4*)&As[kk][ty * 8 + 4];
            *(float4*)(br)     = *(const float4*)&Bs[kk][tx * 8];
            *(float4*)(br + 4) = *(const float4*)&Bs[kk][tx * 8 + 4];
            #pragma unroll
            for (int i = 0; i < 8; i++)
                #pragma unroll
                for (int j = 0; j < 8; j++)
                    acc[i][j] = fmaf(ar[i], br[j], acc[i][j]);
        }
        __syncthreads();
    }
    #pragma unroll
    for (int i = 0; i < 8; i++) {
        float* Cr = C + (size_t)(m0 + ty * 8 + i) * N + n0 + tx * 8;
        #pragma unroll
        for (int j = 0; j < 8; j++)
            Cr[j] = acc[i][j] + bias[n0 + tx * 8 + j];
    }
}

// ---------------- QK^T + distance bias ---------------------------------------
// grid: (ktile=8, qtile=8, bh=192), 256 threads, 64x64 tile, 4x4 per thread.
__global__ void __launch_bounds__(256) attn_scores(
        const float* __restrict__ q, const float* __restrict__ k,
        const float* __restrict__ dist_emb, float* __restrict__ att) {
    int bh = blockIdx.z;
    int b = bh / H_, h = bh % H_;
    int q0 = blockIdx.y * 64, k0 = blockIdx.x * 64;
    __shared__ float Qs[64][65];
    __shared__ float Ks[64][65];
    int tid = threadIdx.x;
    const float* qbase = q + ((size_t)(b * N_ + q0)) * D_ + h * DK_;
    const float* kbase = k + ((size_t)(b * N_ + k0)) * D_ + h * DK_;
    for (int e = tid; e < 1024; e += 256) {
        int r = e >> 4, c4 = (e & 15) << 2;
        float4 qa = *(const float4*)(qbase + (size_t)r * D_ + c4);
        Qs[r][c4] = qa.x; Qs[r][c4 + 1] = qa.y; Qs[r][c4 + 2] = qa.z; Qs[r][c4 + 3] = qa.w;
        float4 ka = *(const float4*)(kbase + (size_t)r * D_ + c4);
        Ks[r][c4] = ka.x; Ks[r][c4 + 1] = ka.y; Ks[r][c4 + 2] = ka.z; Ks[r][c4 + 3] = ka.w;
    }
    __syncthreads();
    int tx = tid & 15, ty = tid >> 4;
    float acc[4][4];
    #pragma unroll
    for (int i = 0; i < 4; i++)
        #pragma unroll
        for (int j = 0; j < 4; j++) acc[i][j] = 0.0f;
    #pragma unroll 16
    for (int kk = 0; kk < 64; kk++) {
        float ar[4], br[4];
        #pragma unroll
        for (int i = 0; i < 4; i++) ar[i] = Qs[ty * 4 + i][kk];
        #pragma unroll
        for (int j = 0; j < 4; j++) br[j] = Ks[tx * 4 + j][kk];
        #pragma unroll
        for (int i = 0; i < 4; i++)
            #pragma unroll
            for (int j = 0; j < 4; j++)
                acc[i][j] = fmaf(ar[i], br[j], acc[i][j]);
    }
    float pxq[4], pyq[4], pxk[4], pyk[4];
    #pragma unroll
    for (int i = 0; i < 4; i++) {
        pxq[i] = g_px[b * N_ + q0 + ty * 4 + i];
        pyq[i] = g_py[b * N_ + q0 + ty * 4 + i];
        pxk[i] = g_px[b * N_ + k0 + tx * 4 + i];
        pyk[i] = g_py[b * N_ + k0 + tx * 4 + i];
    }
    const float scale = 0.125f;  // 1/sqrt(64)
    #pragma unroll
    for (int i = 0; i < 4; i++) {
        float* ar_out = att + ((size_t)bh * N_ + q0 + ty * 4 + i) * N_ + k0 + tx * 4;
        #pragma unroll
        for (int j = 0; j < 4; j++) {
            float dx = pxk[j] - pxq[i];
            float dy = pyk[j] - pyq[i];
            int bin = (int)(sqrtf(dx * dx + dy * dy) * 2.0f);
            ar_out[j] = acc[i][j] * scale + dist_emb[bin * H_ + h];
        }
    }
}

// ---------------- row softmax (512 per row) ----------------------------------
__global__ void softmax_kernel(float* __restrict__ att) {
    float* rowp = att + (size_t)blockIdx.x * N_;
    int t = threadIdx.x;
    float a0 = rowp[t], a1 = rowp[t + 256];
    __shared__ float red[256];
    red[t] = fmaxf(a0, a1);
    __syncthreads();
    for (int off = 128; off > 0; off >>= 1) {
        if (t < off) red[t] = fmaxf(red[t], red[t + off]);
        __syncthreads();
    }
    float m = red[0];
    __syncthreads();
    float e0 = __expf(a0 - m), e1 = __expf(a1 - m);
    red[t] = e0 + e1;
    __syncthreads();
    for (int off = 128; off > 0; off >>= 1) {
        if (t < off) red[t] += red[t + off];
        __syncthreads();
    }
    float inv = 1.0f / red[0];
    rowp[t] = e0 * inv;
    rowp[t + 256] = e1 * inv;
}

// ---------------- att @ V  ---------------------------------------------------
// grid: (qtile=8, bh=192). Output 64x64 (q x dk), K=512 in 64-chunks.
__global__ void __launch_bounds__(256) attn_av(
        const float* __restrict__ att, const float* __restrict__ v) {
    int bh = blockIdx.y;
    int b = bh / H_, h = bh % H_;
    int q0 = blockIdx.x * 64;
    __shared__ float As[64][65];
    __shared__ float Vs[64][65];
    int tid = threadIdx.x, tx = tid & 15, ty = tid >> 4;
    float acc[4][4];
    #pragma unroll
    for (int i = 0; i < 4; i++)
        #pragma unroll
        for (int j = 0; j < 4; j++) acc[i][j] = 0.0f;

    for (int k0 = 0; k0 < N_; k0 += 64) {
        for (int e = tid; e < 1024; e += 256) {
            int r = e >> 4, c4 = (e & 15) << 2;
            float4 a4 = *(const float4*)(att + ((size_t)bh * N_ + q0 + r) * N_ + k0 + c4);
            As[r][c4] = a4.x; As[r][c4 + 1] = a4.y; As[r][c4 + 2] = a4.z; As[r][c4 + 3] = a4.w;
            float4 v4 = *(const float4*)(v + ((size_t)(b * N_ + k0 + r)) * D_ + h * DK_ + c4);
            Vs[r][c4] = v4.x; Vs[r][c4 + 1] = v4.y; Vs[r][c4 + 2] = v4.z; Vs[r][c4 + 3] = v4.w;
        }
        __syncthreads();
        #pragma unroll 16
        for (int kk = 0; kk < 64; kk++) {
            float ar[4], br[4];
            #pragma unroll
            for (int i = 0; i < 4; i++) ar[i] = As[ty * 4 + i][kk];
            #pragma unroll
            for (int j = 0; j < 4; j++) br[j] = Vs[kk][tx * 4 + j];
            #pragma unroll
            for (int i = 0; i < 4; i++)
                #pragma unroll
                for (int j = 0; j < 4; j++)
                    acc[i][j] = fmaf(ar[i], br[j], acc[i][j]);
        }
        __syncthreads();
    }
    #pragma unroll
    for (int i = 0; i < 4; i++) {
        float* cr = g_ctx + ((size_t)(b * N_ + q0 + ty * 4 + i)) * D_ + h * DK_ + tx * 4;
        #pragma unroll
        for (int j = 0; j < 4; j++) cr[j] = acc[i][j];
    }
}

// ---------------- launcher ---------------------------------------------------
extern "C" void kernel_launch(void* const* d_in, const int* in_sizes, int n_in,
                              void* d_out, int out_size) {
    const float* features    = (const float*)d_in[0];
    const float* boxes       = (const float*)d_in[1];
    const int*   image_sizes = (const int*)  d_in[2];
    const float* Wq = (const float*)d_in[3];
    const float* bq = (const float*)d_in[4];
    const float* Wk = (const float*)d_in[5];
    const float* bk = (const float*)d_in[6];
    const float* Wv = (const float*)d_in[7];
    const float* bv = (const float*)d_in[8];
    const float* Wo = (const float*)d_in[9];
    const float* bo = (const float*)d_in[10];
    const float* gamma = (const float*)d_in[11];
    const float* beta  = (const float*)d_in[12];
    const float* dist  = (const float*)d_in[13];

    float* out = (float*)d_out;
    float* att = out + OUT_OFF;

    void *px_ = 0, *pq = 0, *pk = 0, *pv = 0, *pctx = 0;
    cudaGetSymbolAddress(&px_,  g_x);
    cudaGetSymbolAddress(&pq,   g_q);
    cudaGetSymbolAddress(&pk,   g_k);
    cudaGetSymbolAddress(&pv,   g_v);
    cudaGetSymbolAddress(&pctx, g_ctx);
    float* xx  = (float*)px_;
    float* qq  = (float*)pq;
    float* kk  = (float*)pk;
    float* vv  = (float*)pv;
    float* ctx = (float*)pctx;

    ln_kernel<<<ROWS, 256>>>(features, gamma, beta);
    patch_kernel<<<(ROWS + 255) / 256, 256>>>(boxes, image_sizes);

    dim3 ggrid(D_ / 128, ROWS / 128);   // (6, 64)
    gemm_bias<<<ggrid, 256>>>(xx, Wq, bq, qq, ROWS, D_, D_);
    gemm_bias<<<ggrid, 256>>>(xx, Wk, bk, kk, ROWS, D_, D_);
    gemm_bias<<<ggrid, 256>>>(xx, Wv, bv, vv, ROWS, D_, D_);

    dim3 sgrid(N_ / 64, N_ / 64, B_ * H_);  // (8, 8, 192)
    attn_scores<<<sgrid, 256>>>(qq, kk, dist, att);

    softmax_kernel<<<B_ * H_ * N_, 256>>>(att);

    dim3 avgrid(N_ / 64, B_ * H_);  // (8, 192)
    attn_av<<<avgrid, 256>>>(att, vv);

    gemm_bias<<<ggrid, 256>>>(ctx, Wo, bo, out, ROWS, D_, D_);
}

// round 6
// speedup vs baseline: 3.0954x; 3.0954x over previous
#include <cuda_runtime.h>
#include <math.h>
#include <stdint.h>

#define B_   16
#define N_   512
#define D_   768
#define H_   12
#define DK_  64
#define ROWS (B_*N_)                 // 8192
#define OUT_OFF ((size_t)ROWS*D_)    // 6291456
#define WSZ (D_*D_)                  // 589824

// ---------------- scratch (static device globals; no allocation) -------------
__device__ float g_x[ROWS*D_];
__device__ float g_q[ROWS*D_];
__device__ float g_k[ROWS*D_];
__device__ float g_v[ROWS*D_];
__device__ float g_ctx[ROWS*D_];
__device__ float g_px[ROWS];
__device__ float g_py[ROWS];
__device__ float g_wc[4*WSZ];        // tf32-rounded Wq,Wk,Wv,Wo

// ---------------- helpers ----------------------------------------------------
__device__ __forceinline__ float to_tf32(float x) {
    float y;
    asm("cvt.rna.tf32.f32 %0, %1;" : "=f"(y) : "f"(x));
    return y;
}

__device__ __forceinline__ void mma8(float* c, const uint32_t* a, const uint32_t* b) {
    asm volatile(
        "mma.sync.aligned.m16n8k8.row.col.f32.tf32.tf32.f32 "
        "{%0,%1,%2,%3},{%4,%5,%6,%7},{%8,%9},{%0,%1,%2,%3};\n"
        : "+f"(c[0]), "+f"(c[1]), "+f"(c[2]), "+f"(c[3])
        : "r"(a[0]), "r"(a[1]), "r"(a[2]), "r"(a[3]), "r"(b[0]), "r"(b[1]));
}

__device__ __forceinline__ void cp16(void* s, const void* g) {
    uint32_t sa = (uint32_t)__cvta_generic_to_shared(s);
    asm volatile("cp.async.cg.shared.global [%0], [%1], 16;\n" :: "r"(sa), "l"(g));
}

// ---------------- LayerNorm (tf32-rounded output) ----------------------------
__global__ void ln_kernel(const float* __restrict__ f,
                          const float* __restrict__ gamma,
                          const float* __restrict__ beta) {
    int row = blockIdx.x;
    int t = threadIdx.x;
    const float* fr = f + (size_t)row * D_;
    float v0 = fr[t], v1 = fr[t + 256], v2 = fr[t + 512];
    __shared__ float red[256];
    red[t] = v0 + v1 + v2;
    __syncthreads();
    for (int off = 128; off > 0; off >>= 1) {
        if (t < off) red[t] += red[t + off];
        __syncthreads();
    }
    float mu = red[0] * (1.0f / D_);
    __syncthreads();
    float d0 = v0 - mu, d1 = v1 - mu, d2 = v2 - mu;
    red[t] = d0 * d0 + d1 * d1 + d2 * d2;
    __syncthreads();
    for (int off = 128; off > 0; off >>= 1) {
        if (t < off) red[t] += red[t + off];
        __syncthreads();
    }
    float rstd = rsqrtf(red[0] * (1.0f / D_) + 1e-5f);
    float* xr = g_x + (size_t)row * D_;
    xr[t]       = to_tf32(d0 * rstd * gamma[t]       + beta[t]);
    xr[t + 256] = to_tf32(d1 * rstd * gamma[t + 256] + beta[t + 256]);
    xr[t + 512] = to_tf32(d2 * rstd * gamma[t + 512] + beta[t + 512]);
}

// ---------------- weight tf32 prepass ----------------------------------------
__global__ void cvt_w(const float* __restrict__ a, const float* __restrict__ b,
                      const float* __restrict__ c, const float* __restrict__ d) {
    int i = blockIdx.x * 256 + threadIdx.x;
    g_wc[i]           = to_tf32(a[i]);
    g_wc[i + WSZ]     = to_tf32(b[i]);
    g_wc[i + 2*WSZ]   = to_tf32(c[i]);
    g_wc[i + 3*WSZ]   = to_tf32(d[i]);
}

// ---------------- patch bins --------------------------------------------------
__global__ void patch_kernel(const float* __restrict__ boxes,
                             const int* __restrict__ image_sizes) {
    int i = blockIdx.x * blockDim.x + threadIdx.x;
    if (i >= ROWS) return;
    int b = i / N_;
    float w = (float)image_sizes[b * 4 + 0];
    float h = (float)image_sizes[b * 4 + 1];
    const float* bx = boxes + (size_t)i * 4;
    float x0 = bx[0] * w, y0 = bx[1] * h, x1 = bx[2] * w, y1 = bx[3] * h;
    float spw = floorf(w / 11.0f);
    float sph = floorf(h / 11.0f);
    float cx = floorf((x0 + x1) / 2.0f);
    float cy = floorf((y0 + y1) / 2.0f);
    float px = 0.0f, py = 0.0f;
    for (int j = 0; j < 11; j++) {
        float lo = (float)j * spw, hi = (float)(j + 1) * spw;
        if (lo <= cx && cx <= hi) { px = (float)j; break; }
    }
    for (int j = 0; j < 11; j++) {
        float lo = (float)j * sph, hi = (float)(j + 1) * sph;
        if (lo <= cy && cy <= hi) { py = (float)j; break; }
    }
    g_px[i] = px;
    g_py[i] = py;
}

// ---------------- tf32 tensor-core GEMM: C = A[M,768] @ W[768,768]^T + bias ---
// 128x128 tile, BK=32, 256 threads (8 warps = 2x4), cp.async double-buffered.
#define GEMM_SMEM (2*2*128*36*4)   // 73728 bytes
__global__ void __launch_bounds__(256, 2) gemm_tc(
        const float* __restrict__ A, const float* __restrict__ W,
        const float* __restrict__ bias, float* __restrict__ C, int cvt_out) {
    extern __shared__ float sm[];
    float* As = sm;                 // [2][128][36]
    float* Ws = sm + 2 * 128 * 36;  // [2][128][36]
    int tid = threadIdx.x;
    int w = tid >> 5, lane = tid & 31, g = lane >> 2, tig = lane & 3;
    int wm = w >> 2, wn = w & 3;    // wm: 0..1 (64 rows), wn: 0..3 (32 cols)
    int m0 = blockIdx.y * 128, n0 = blockIdx.x * 128;

    float acc[4][4][4];
    #pragma unroll
    for (int i = 0; i < 4; i++)
        #pragma unroll
        for (int j = 0; j < 4; j++)
            #pragma unroll
            for (int q = 0; q < 4; q++) acc[i][j][q] = 0.0f;

    #define LOAD_STAGE(kt, s)                                                   \
        {                                                                       \
            int k0_ = (kt) * 32;                                                \
            _Pragma("unroll")                                                   \
            for (int j = 0; j < 4; j++) {                                       \
                int i_ = tid + 256 * j;                                         \
                int r_ = i_ >> 3, c_ = (i_ & 7) * 4;                            \
                cp16(As + (s) * 4608 + r_ * 36 + c_,                            \
                     A + (size_t)(m0 + r_) * 768 + k0_ + c_);                   \
                cp16(Ws + (s) * 4608 + r_ * 36 + c_,                            \
                     W + (size_t)(n0 + r_) * 768 + k0_ + c_);                   \
            }                                                                   \
            asm volatile("cp.async.commit_group;\n");                           \
        }

    LOAD_STAGE(0, 0);
    for (int kt = 0; kt < 24; kt++) {
        if (kt + 1 < 24) {
            LOAD_STAGE(kt + 1, (kt + 1) & 1);
        } else {
            asm volatile("cp.async.commit_group;\n");
        }
        asm volatile("cp.async.wait_group 1;\n");
        __syncthreads();
        int s = kt & 1;
        float* Ab = As + s * 4608;
        float* Wb = Ws + s * 4608;
        #pragma unroll
        for (int st = 0; st < 4; st++) {
            int kc = st * 8 + tig;
            uint32_t a[4][4];
            #pragma unroll
            for (int mt = 0; mt < 4; mt++) {
                int r = wm * 64 + mt * 16 + g;
                a[mt][0] = __float_as_uint(Ab[r * 36 + kc]);
                a[mt][1] = __float_as_uint(Ab[(r + 8) * 36 + kc]);
                a[mt][2] = __float_as_uint(Ab[r * 36 + kc + 4]);
                a[mt][3] = __float_as_uint(Ab[(r + 8) * 36 + kc + 4]);
            }
            uint32_t bb[4][2];
            #pragma unroll
            for (int nt = 0; nt < 4; nt++) {
                int n = wn * 32 + nt * 8 + g;
                bb[nt][0] = __float_as_uint(Wb[n * 36 + kc]);
                bb[nt][1] = __float_as_uint(Wb[n * 36 + kc + 4]);
            }
            #pragma unroll
            for (int mt = 0; mt < 4; mt++)
                #pragma unroll
                for (int nt = 0; nt < 4; nt++)
                    mma8(acc[mt][nt], a[mt], bb[nt]);
        }
        __syncthreads();
    }

    #pragma unroll
    for (int mt = 0; mt < 4; mt++) {
        #pragma unroll
        for (int nt = 0; nt < 4; nt++) {
            int col = n0 + wn * 32 + nt * 8 + 2 * tig;
            float bx = bias[col], by = bias[col + 1];
            #pragma unroll
            for (int half = 0; half < 2; half++) {
                int row = m0 + wm * 64 + mt * 16 + g + half * 8;
                float2 t;
                t.x = acc[mt][nt][half * 2] + bx;
                t.y = acc[mt][nt][half * 2 + 1] + by;
                if (cvt_out) { t.x = to_tf32(t.x); t.y = to_tf32(t.y); }
                *(float2*)(C + (size_t)row * 768 + col) = t;
            }
        }
    }
}

// ---------------- fused attention: scores + bias + softmax + AV ---------------
// block = (qtile 64, bh). 512 threads (16 warps = 4x4).
// K/V tiles double-buffered via cp.async. Dynamic smem ~178KB.
#define ATT_LD 516
#define ATT_SMEM ((64*ATT_LD + 64*68 + 2*64*68 + 128 + 1024 + 384)*4)
__global__ void __launch_bounds__(512) attn_fused(
        const float* __restrict__ q, const float* __restrict__ k,
        const float* __restrict__ v, const float* __restrict__ dist_emb,
        float* __restrict__ att, float* __restrict__ ctx,
        const float* __restrict__ px, const float* __restrict__ py) {
    extern __shared__ float sm[];
    float* att_s = sm;                        // [64][516]
    float* q_s   = att_s + 64 * ATT_LD;       // [64][68]
    float* kv_s  = q_s + 64 * 68;             // [2][64][68] double buffer
    float* pxq   = kv_s + 2 * 64 * 68;        // 64
    float* pyq   = pxq + 64;                  // 64
    float* pxk   = pyq + 64;                  // 512
    float* pyk   = pxk + 512;                 // 512
    float* emb   = pyk + 512;                 // 384

    int bh = blockIdx.y;
    int b = bh / H_, h = bh % H_;
    int q0 = blockIdx.x * 64;
    int tid = threadIdx.x;
    int w = tid >> 5, lane = tid & 31, g = lane >> 2, tig = lane & 3;
    int wm = w >> 2, wn = w & 3;   // 4x4 warps over 64x64

    // async tile loader: 64 rows x 64 cols -> kv_s[s]
    #define LOAD_KV(base_ptr, s)                                                \
        {                                                                       \
            const float* _p = (base_ptr);                                       \
            _Pragma("unroll")                                                   \
            for (int e2 = 0; e2 < 2; e2++) {                                    \
                int e = tid + 512 * e2;                                         \
                int r = e >> 4, c = (e & 15) << 2;                              \
                cp16(kv_s + (s) * 4352 + r * 68 + c,                            \
                     _p + (size_t)r * D_ + c);                                  \
            }                                                                   \
            asm volatile("cp.async.commit_group;\n");                           \
        }

    // loads: Q tile + patch data + emb; prefetch first K tile
    {
        const float* kb0 = k + ((size_t)(b * N_)) * D_ + h * DK_;
        LOAD_KV(kb0, 0);
        const float* qb = q + ((size_t)(b * N_ + q0)) * D_ + h * DK_;
        for (int e = tid; e < 1024; e += 512) {
            int r = e >> 4, c = (e & 15) << 2;
            float4 t = *(const float4*)(qb + (size_t)r * D_ + c);
            float* d = q_s + r * 68 + c;
            d[0] = t.x; d[1] = t.y; d[2] = t.z; d[3] = t.w;
        }
        if (tid < 64) { pxq[tid] = px[b * N_ + q0 + tid]; pyq[tid] = py[b * N_ + q0 + tid]; }
        pxk[tid] = px[b * N_ + tid];
        pyk[tid] = py[b * N_ + tid];
        if (tid < 384) emb[tid] = dist_emb[tid];
    }

    // ---- scores + dist bias into att_s ----
    for (int kt = 0; kt < 8; kt++) {
        int k0 = kt * 64;
        if (kt + 1 < 8) {
            const float* kb = k + ((size_t)(b * N_ + k0 + 64)) * D_ + h * DK_;
            LOAD_KV(kb, (kt + 1) & 1);
        } else {
            asm volatile("cp.async.commit_group;\n");
        }
        asm volatile("cp.async.wait_group 1;\n");
        __syncthreads();
        float* kb_s = kv_s + (kt & 1) * 4352;
        float acc[2][4];
        #pragma unroll
        for (int nt = 0; nt < 2; nt++)
            #pragma unroll
            for (int i = 0; i < 4; i++) acc[nt][i] = 0.0f;
        #pragma unroll
        for (int st = 0; st < 8; st++) {
            int ac = st * 8 + tig;
            int arow = wm * 16 + g;
            uint32_t a[4];
            a[0] = __float_as_uint(q_s[arow * 68 + ac]);
            a[1] = __float_as_uint(q_s[(arow + 8) * 68 + ac]);
            a[2] = __float_as_uint(q_s[arow * 68 + ac + 4]);
            a[3] = __float_as_uint(q_s[(arow + 8) * 68 + ac + 4]);
            #pragma unroll
            for (int nt = 0; nt < 2; nt++) {
                int brow = wn * 16 + nt * 8 + g;
                uint32_t bb[2];
                bb[0] = __float_as_uint(kb_s[brow * 68 + ac]);
                bb[1] = __float_as_uint(kb_s[brow * 68 + ac + 4]);
                mma8(acc[nt], a, bb);
            }
        }
        int row0 = wm * 16 + g;
        #pragma unroll
        for (int nt = 0; nt < 2; nt++) {
            int col0 = wn * 16 + nt * 8 + 2 * tig;
            #pragma unroll
            for (int half = 0; half < 2; half++) {
                int r = row0 + half * 8;
                float fx = pxq[r], fy = pyq[r];
                #pragma unroll
                for (int cc = 0; cc < 2; cc++) {
                    int c = col0 + cc;
                    float dx = pxk[k0 + c] - fx, dy = pyk[k0 + c] - fy;
                    int bin = (int)(sqrtf(dx * dx + dy * dy) * 2.0f);
                    att_s[r * ATT_LD + k0 + c] =
                        acc[nt][half * 2 + cc] * 0.125f + emb[bin * H_ + h];
                }
            }
        }
        __syncthreads();
    }

    // prefetch first V tile while softmax runs
    {
        const float* vb0 = v + ((size_t)(b * N_)) * D_ + h * DK_;
        LOAD_KV(vb0, 0);
    }

    // ---- softmax: each warp handles 4 rows; write att to gmem + tf32 to smem ----
    {
        #pragma unroll
        for (int rr = 0; rr < 4; rr++) {
            int r = w * 4 + rr;
            float* rp = att_s + r * ATT_LD;
            float vals[16];
            float m = -1e30f;
            #pragma unroll
            for (int i = 0; i < 16; i++) { vals[i] = rp[lane + 32 * i]; m = fmaxf(m, vals[i]); }
            #pragma unroll
            for (int off = 16; off; off >>= 1) m = fmaxf(m, __shfl_xor_sync(0xffffffffu, m, off));
            float s = 0.0f;
            #pragma unroll
            for (int i = 0; i < 16; i++) { vals[i] = __expf(vals[i] - m); s += vals[i]; }
            #pragma unroll
            for (int off = 16; off; off >>= 1) s += __shfl_xor_sync(0xffffffffu, s, off);
            float inv = 1.0f / s;
            float* go = att + ((size_t)bh * N_ + q0 + r) * N_;
            #pragma unroll
            for (int i = 0; i < 16; i++) {
                float o = vals[i] * inv;
                go[lane + 32 * i] = o;
                rp[lane + 32 * i] = to_tf32(o);
            }
        }
    }
    __syncthreads();

    // ---- AV: ctx[64 x 64] = att_s[64 x 512] @ V[512 x 64] ----
    float acc2[2][4];
    #pragma unroll
    for (int nt = 0; nt < 2; nt++)
        #pragma unroll
        for (int i = 0; i < 4; i++) acc2[nt][i] = 0.0f;

    for (int jt = 0; jt < 8; jt++) {
        int j0 = jt * 64;
        if (jt + 1 < 8) {
            const float* vb = v + ((size_t)(b * N_ + j0 + 64)) * D_ + h * DK_;
            LOAD_KV(vb, (jt + 1) & 1);
        } else {
            asm volatile("cp.async.commit_group;\n");
        }
        asm volatile("cp.async.wait_group 1;\n");
        __syncthreads();
        float* vb_s = kv_s + (jt & 1) * 4352;
        #pragma unroll
        for (int st = 0; st < 8; st++) {
            int arow = wm * 16 + g;
            int ac = j0 + st * 8 + tig;
            uint32_t a[4];
            a[0] = __float_as_uint(att_s[arow * ATT_LD + ac]);
            a[1] = __float_as_uint(att_s[(arow + 8) * ATT_LD + ac]);
            a[2] = __float_as_uint(att_s[arow * ATT_LD + ac + 4]);
            a[3] = __float_as_uint(att_s[(arow + 8) * ATT_LD + ac + 4]);
            int krow = st * 8 + tig;
            #pragma unroll
            for (int nt = 0; nt < 2; nt++) {
                int nc = wn * 16 + nt * 8 + g;
                uint32_t bb[2];
                bb[0] = __float_as_uint(vb_s[krow * 68 + nc]);
                bb[1] = __float_as_uint(vb_s[(krow + 4) * 68 + nc]);
                mma8(acc2[nt], a, bb);
            }
        }
        __syncthreads();
    }

    // write ctx (tf32-rounded: feeds out-proj tf32 GEMM)
    {
        int row0 = wm * 16 + g;
        #pragma unroll
        for (int nt = 0; nt < 2; nt++) {
            int col0 = wn * 16 + nt * 8 + 2 * tig;
            #pragma unroll
            for (int half = 0; half < 2; half++) {
                int r = q0 + row0 + half * 8;
                float2 t;
                t.x = to_tf32(acc2[nt][half * 2]);
                t.y = to_tf32(acc2[nt][half * 2 + 1]);
                *(float2*)(ctx + ((size_t)(b * N_ + r)) * D_ + h * DK_ + col0) = t;
            }
        }
    }
}

// ---------------- launcher ---------------------------------------------------
extern "C" void kernel_launch(void* const* d_in, const int* in_sizes, int n_in,
                              void* d_out, int out_size) {
    const float* features    = (const float*)d_in[0];
    const float* boxes       = (const float*)d_in[1];
    const int*   image_sizes = (const int*)  d_in[2];
    const float* Wq = (const float*)d_in[3];
    const float* bq = (const float*)d_in[4];
    const float* Wk = (const float*)d_in[5];
    const float* bk = (const float*)d_in[6];
    const float* Wv = (const float*)d_in[7];
    const float* bv = (const float*)d_in[8];
    const float* Wo = (const float*)d_in[9];
    const float* bo = (const float*)d_in[10];
    const float* gamma = (const float*)d_in[11];
    const float* beta  = (const float*)d_in[12];
    const float* dist  = (const float*)d_in[13];

    float* out = (float*)d_out;
    float* att = out + OUT_OFF;

    void *p0 = 0, *p1 = 0, *p2 = 0, *p3 = 0, *p4 = 0, *p5 = 0, *p6 = 0, *p7 = 0;
    cudaGetSymbolAddress(&p0, g_x);
    cudaGetSymbolAddress(&p1, g_q);
    cudaGetSymbolAddress(&p2, g_k);
    cudaGetSymbolAddress(&p3, g_v);
    cudaGetSymbolAddress(&p4, g_ctx);
    cudaGetSymbolAddress(&p5, g_px);
    cudaGetSymbolAddress(&p6, g_py);
    cudaGetSymbolAddress(&p7, g_wc);
    float* xx  = (float*)p0;
    float* qq  = (float*)p1;
    float* kk  = (float*)p2;
    float* vv  = (float*)p3;
    float* ctx = (float*)p4;
    float* px  = (float*)p5;
    float* py  = (float*)p6;
    float* wc  = (float*)p7;

    cudaFuncSetAttribute(gemm_tc, cudaFuncAttributeMaxDynamicSharedMemorySize, GEMM_SMEM);
    cudaFuncSetAttribute(attn_fused, cudaFuncAttributeMaxDynamicSharedMemorySize, ATT_SMEM);

    ln_kernel<<<ROWS, 256>>>(features, gamma, beta);
    patch_kernel<<<(ROWS + 255) / 256, 256>>>(boxes, image_sizes);
    cvt_w<<<WSZ / 256, 256>>>(Wq, Wk, Wv, Wo);

    dim3 ggrid(D_ / 128, ROWS / 128);  // (6, 64)
    gemm_tc<<<ggrid, 256, GEMM_SMEM>>>(xx, wc,           bq, qq, 1);
    gemm_tc<<<ggrid, 256, GEMM_SMEM>>>(xx, wc + WSZ,     bk, kk, 1);
    gemm_tc<<<ggrid, 256, GEMM_SMEM>>>(xx, wc + 2 * WSZ, bv, vv, 1);

    dim3 agrid(N_ / 64, B_ * H_);      // (8, 192)
    attn_fused<<<agrid, 512, ATT_SMEM>>>(qq, kk, vv, dist, att, ctx, px, py);

    gemm_tc<<<ggrid, 256, GEMM_SMEM>>>(ctx, wc + 3 * WSZ, bo, out, 0);
}

// round 8
// speedup vs baseline: 3.4027x; 1.0993x over previous
#include <cuda_runtime.h>
#include <math.h>
#include <stdint.h>

#define B_   16
#define N_   512
#define D_   768
#define H_   12
#define DK_  64
#define ROWS (B_*N_)                 // 8192
#define OUT_OFF ((size_t)ROWS*D_)    // 6291456
#define WSZ (D_*D_)                  // 589824
#define QKVW 2304                    // packed qkv width

// ---------------- scratch (static device globals; no allocation) -------------
__device__ float g_x[ROWS*D_];
__device__ float g_qkv[(size_t)ROWS*QKVW];
__device__ float g_ctx[ROWS*D_];
__device__ float g_px[ROWS];
__device__ float g_py[ROWS];
__device__ float g_wc[4*WSZ];        // tf32 Wq,Wk,Wv rows 0..2303 then Wo
__device__ float g_bc[QKVW];         // packed bq|bk|bv
__device__ unsigned char g_bins[(size_t)B_*N_*N_];   // 4MB distance bins

// ---------------- helpers ----------------------------------------------------
__device__ __forceinline__ float to_tf32(float x) {
    float y;
    asm("cvt.rna.tf32.f32 %0, %1;" : "=f"(y) : "f"(x));
    return y;
}

__device__ __forceinline__ void mma8(float* c, const uint32_t* a, const uint32_t* b) {
    asm volatile(
        "mma.sync.aligned.m16n8k8.row.col.f32.tf32.tf32.f32 "
        "{%0,%1,%2,%3},{%4,%5,%6,%7},{%8,%9},{%0,%1,%2,%3};\n"
        : "+f"(c[0]), "+f"(c[1]), "+f"(c[2]), "+f"(c[3])
        : "r"(a[0]), "r"(a[1]), "r"(a[2]), "r"(a[3]), "r"(b[0]), "r"(b[1]));
}

__device__ __forceinline__ void cp16(void* s, const void* g) {
    uint32_t sa = (uint32_t)__cvta_generic_to_shared(s);
    asm volatile("cp.async.cg.shared.global [%0], [%1], 16;\n" :: "r"(sa), "l"(g));
}

// ---------------- LayerNorm (tf32-rounded output) ----------------------------
__global__ void ln_kernel(const float* __restrict__ f,
                          const float* __restrict__ gamma,
                          const float* __restrict__ beta) {
    int row = blockIdx.x;
    int t = threadIdx.x;
    const float* fr = f + (size_t)row * D_;
    float v0 = fr[t], v1 = fr[t + 256], v2 = fr[t + 512];
    __shared__ float red[256];
    red[t] = v0 + v1 + v2;
    __syncthreads();
    for (int off = 128; off > 0; off >>= 1) {
        if (t < off) red[t] += red[t + off];
        __syncthreads();
    }
    float mu = red[0] * (1.0f / D_);
    __syncthreads();
    float d0 = v0 - mu, d1 = v1 - mu, d2 = v2 - mu;
    red[t] = d0 * d0 + d1 * d1 + d2 * d2;
    __syncthreads();
    for (int off = 128; off > 0; off >>= 1) {
        if (t < off) red[t] += red[t + off];
        __syncthreads();
    }
    float rstd = rsqrtf(red[0] * (1.0f / D_) + 1e-5f);
    float* xr = g_x + (size_t)row * D_;
    xr[t]       = to_tf32(d0 * rstd * gamma[t]       + beta[t]);
    xr[t + 256] = to_tf32(d1 * rstd * gamma[t + 256] + beta[t + 256]);
    xr[t + 512] = to_tf32(d2 * rstd * gamma[t + 512] + beta[t + 512]);
}

// ---------------- weight tf32 prepass + bias pack ----------------------------
__global__ void cvt_w(const float* __restrict__ a, const float* __restrict__ b,
                      const float* __restrict__ c, const float* __restrict__ d,
                      const float* __restrict__ bq, const float* __restrict__ bk,
                      const float* __restrict__ bv) {
    int i = blockIdx.x * 256 + threadIdx.x;
    g_wc[i]           = to_tf32(a[i]);
    g_wc[i + WSZ]     = to_tf32(b[i]);
    g_wc[i + 2*WSZ]   = to_tf32(c[i]);
    g_wc[i + 3*WSZ]   = to_tf32(d[i]);
    if (i < QKVW) {
        g_bc[i] = (i < 768) ? bq[i] : (i < 1536) ? bk[i - 768] : bv[i - 1536];
    }
}

// ---------------- patch bins --------------------------------------------------
__global__ void patch_kernel(const float* __restrict__ boxes,
                             const int* __restrict__ image_sizes) {
    int i = blockIdx.x * blockDim.x + threadIdx.x;
    if (i >= ROWS) return;
    int b = i / N_;
    float w = (float)image_sizes[b * 4 + 0];
    float h = (float)image_sizes[b * 4 + 1];
    const float* bx = boxes + (size_t)i * 4;
    float x0 = bx[0] * w, y0 = bx[1] * h, x1 = bx[2] * w, y1 = bx[3] * h;
    float spw = floorf(w / 11.0f);
    float sph = floorf(h / 11.0f);
    float cx = floorf((x0 + x1) / 2.0f);
    float cy = floorf((y0 + y1) / 2.0f);
    float px = 0.0f, py = 0.0f;
    for (int j = 0; j < 11; j++) {
        float lo = (float)j * spw, hi = (float)(j + 1) * spw;
        if (lo <= cx && cx <= hi) { px = (float)j; break; }
    }
    for (int j = 0; j < 11; j++) {
        float lo = (float)j * sph, hi = (float)(j + 1) * sph;
        if (lo <= cy && cy <= hi) { py = (float)j; break; }
    }
    g_px[i] = px;
    g_py[i] = py;
}

// ---------------- dist-bin prepass: one block per (b, q) ---------------------
__global__ void bins_kernel() {
    int bq = blockIdx.x;              // 0..8191
    int b = bq >> 9;
    int kcol = threadIdx.x;           // 0..511
    float fx = g_px[bq], fy = g_py[bq];
    float dx = g_px[b * N_ + kcol] - fx;
    float dy = g_py[b * N_ + kcol] - fy;
    int bin = (int)(sqrtf(dx * dx + dy * dy) * 2.0f);
    g_bins[(size_t)bq * N_ + kcol] = (unsigned char)bin;
}

// ---------------- tf32 tensor-core GEMM: C = A[M,768] @ W[?,768]^T + bias ----
// 128x128 tile, BK=32, 256 threads (8 warps = 2x4), cp.async double-buffered.
#define GEMM_SMEM (2*2*128*36*4)   // 73728 bytes
__global__ void __launch_bounds__(256, 2) gemm_tc(
        const float* __restrict__ A, const float* __restrict__ W,
        const float* __restrict__ bias, float* __restrict__ C,
        int ldc, int cvt_out) {
    extern __shared__ float sm[];
    float* As = sm;                 // [2][128][36]
    float* Ws = sm + 2 * 128 * 36;  // [2][128][36]
    int tid = threadIdx.x;
    int w = tid >> 5, lane = tid & 31, g = lane >> 2, tig = lane & 3;
    int wm = w >> 2, wn = w & 3;
    int m0 = blockIdx.y * 128, n0 = blockIdx.x * 128;

    float acc[4][4][4];
    #pragma unroll
    for (int i = 0; i < 4; i++)
        #pragma unroll
        for (int j = 0; j < 4; j++)
            #pragma unroll
            for (int q = 0; q < 4; q++) acc[i][j][q] = 0.0f;

    #define LOAD_STAGE(kt, s)                                                   \
        {                                                                       \
            int k0_ = (kt) * 32;                                                \
            _Pragma("unroll")                                                   \
            for (int j = 0; j < 4; j++) {                                       \
                int i_ = tid + 256 * j;                                         \
                int r_ = i_ >> 3, c_ = (i_ & 7) * 4;                            \
                cp16(As + (s) * 4608 + r_ * 36 + c_,                            \
                     A + (size_t)(m0 + r_) * 768 + k0_ + c_);                   \
                cp16(Ws + (s) * 4608 + r_ * 36 + c_,                            \
                     W + (size_t)(n0 + r_) * 768 + k0_ + c_);                   \
            }                                                                   \
            asm volatile("cp.async.commit_group;\n");                           \
        }

    LOAD_STAGE(0, 0);
    for (int kt = 0; kt < 24; kt++) {
        if (kt + 1 < 24) {
            LOAD_STAGE(kt + 1, (kt + 1) & 1);
        } else {
            asm volatile("cp.async.commit_group;\n");
        }
        asm volatile("cp.async.wait_group 1;\n");
        __syncthreads();
        int s = kt & 1;
        float* Ab = As + s * 4608;
        float* Wb = Ws + s * 4608;
        #pragma unroll
        for (int st = 0; st < 4; st++) {
            int kc = st * 8 + tig;
            uint32_t a[4][4];
            #pragma unroll
            for (int mt = 0; mt < 4; mt++) {
                int r = wm * 64 + mt * 16 + g;
                a[mt][0] = __float_as_uint(Ab[r * 36 + kc]);
                a[mt][1] = __float_as_uint(Ab[(r + 8) * 36 + kc]);
                a[mt][2] = __float_as_uint(Ab[r * 36 + kc + 4]);
                a[mt][3] = __float_as_uint(Ab[(r + 8) * 36 + kc + 4]);
            }
            uint32_t bb[4][2];
            #pragma unroll
            for (int nt = 0; nt < 4; nt++) {
                int n = wn * 32 + nt * 8 + g;
                bb[nt][0] = __float_as_uint(Wb[n * 36 + kc]);
                bb[nt][1] = __float_as_uint(Wb[n * 36 + kc + 4]);
            }
            #pragma unroll
            for (int mt = 0; mt < 4; mt++)
                #pragma unroll
                for (int nt = 0; nt < 4; nt++)
                    mma8(acc[mt][nt], a[mt], bb[nt]);
        }
        __syncthreads();
    }

    #pragma unroll
    for (int mt = 0; mt < 4; mt++) {
        #pragma unroll
        for (int nt = 0; nt < 4; nt++) {
            int col = n0 + wn * 32 + nt * 8 + 2 * tig;
            float bx = bias[col], by = bias[col + 1];
            #pragma unroll
            for (int half = 0; half < 2; half++) {
                int row = m0 + wm * 64 + mt * 16 + g + half * 8;
                float2 t;
                t.x = acc[mt][nt][half * 2] + bx;
                t.y = acc[mt][nt][half * 2 + 1] + by;
                if (cvt_out) { t.x = to_tf32(t.x); t.y = to_tf32(t.y); }
                *(float2*)(C + (size_t)row * ldc + col) = t;
            }
        }
    }
}

// ---------------- fused attention: scores + bias + softmax + AV ---------------
// block = (qtile 32, bh). 256 threads (8 warps = 2x4). ~111KB smem -> 2 CTA/SM.
#define ATT_LD 516
#define ATT_SMEM ((32*ATT_LD + 32*68 + 2*64*68 + 384)*4)
__global__ void __launch_bounds__(256, 2) attn_fused(
        const float* __restrict__ qkv, const float* __restrict__ dist_emb,
        float* __restrict__ att, float* __restrict__ ctx) {
    extern __shared__ float sm[];
    float* att_s = sm;                        // [32][516]
    float* q_s   = att_s + 32 * ATT_LD;       // [32][68]
    float* kv_s  = q_s + 32 * 68;             // [2][64][68] double buffer
    float* emb   = kv_s + 2 * 64 * 68;        // 384

    int bh = blockIdx.y;
    int b = bh / H_, h = bh % H_;
    int q0 = blockIdx.x * 32;
    int tid = threadIdx.x;
    int w = tid >> 5, lane = tid & 31, g = lane >> 2, tig = lane & 3;
    int wm = w >> 2, wn = w & 3;   // 2x4 warps over 32x64

    const float* qbase = qkv + (size_t)(b * N_) * QKVW + h * DK_;        // q cols
    const float* kbase = qbase + 768;
    const float* vbase = qbase + 1536;

    // async tile loader: 64 rows x 64 cols -> kv_s[s]; row stride QKVW
    #define LOAD_KV(base_ptr, row0, s)                                          \
        {                                                                       \
            const float* _p = (base_ptr) + (size_t)(row0) * QKVW;               \
            _Pragma("unroll")                                                   \
            for (int e2 = 0; e2 < 4; e2++) {                                    \
                int e = tid + 256 * e2;                                         \
                int r = e >> 4, c = (e & 15) << 2;                              \
                cp16(kv_s + (s) * 4352 + r * 68 + c,                            \
                     _p + (size_t)r * QKVW + c);                                \
            }                                                                   \
            asm volatile("cp.async.commit_group;\n");                           \
        }

    // prefetch first K tile; load Q tile (32x64) + emb
    LOAD_KV(kbase, 0, 0);
    {
        const float* qb = qbase + (size_t)q0 * QKVW;
        #pragma unroll
        for (int e2 = 0; e2 < 2; e2++) {
            int e = tid + 256 * e2;
            int r = e >> 4, c = (e & 15) << 2;
            float4 t = *(const float4*)(qb + (size_t)r * QKVW + c);
            float* d = q_s + r * 68 + c;
            d[0] = t.x; d[1] = t.y; d[2] = t.z; d[3] = t.w;
        }
        for (int i = tid; i < 384; i += 256) emb[i] = dist_emb[i];
    }

    // ---- scores + dist bias into att_s ----
    for (int kt = 0; kt < 8; kt++) {
        int k0 = kt * 64;
        if (kt + 1 < 8) {
            LOAD_KV(kbase, k0 + 64, (kt + 1) & 1);
        } else {
            asm volatile("cp.async.commit_group;\n");
        }
        asm volatile("cp.async.wait_group 1;\n");
        __syncthreads();
        float* kb_s = kv_s + (kt & 1) * 4352;
        float acc[2][4];
        #pragma unroll
        for (int nt = 0; nt < 2; nt++)
            #pragma unroll
            for (int i = 0; i < 4; i++) acc[nt][i] = 0.0f;
        #pragma unroll
        for (int st = 0; st < 8; st++) {
            int ac = st * 8 + tig;
            int arow = wm * 16 + g;
            uint32_t a[4];
            a[0] = __float_as_uint(q_s[arow * 68 + ac]);
            a[1] = __float_as_uint(q_s[(arow + 8) * 68 + ac]);
            a[2] = __float_as_uint(q_s[arow * 68 + ac + 4]);
            a[3] = __float_as_uint(q_s[(arow + 8) * 68 + ac + 4]);
            #pragma unroll
            for (int nt = 0; nt < 2; nt++) {
                int brow = wn * 16 + nt * 8 + g;
                uint32_t bb[2];
                bb[0] = __float_as_uint(kb_s[brow * 68 + ac]);
                bb[1] = __float_as_uint(kb_s[brow * 68 + ac + 4]);
                mma8(acc[nt], a, bb);
            }
        }
        int row0 = wm * 16 + g;
        #pragma unroll
        for (int nt = 0; nt < 2; nt++) {
            int col0 = wn * 16 + nt * 8 + 2 * tig;
            #pragma unroll
            for (int half = 0; half < 2; half++) {
                int r = row0 + half * 8;
                const unsigned char* bp =
                    g_bins + (size_t)(b * N_ + q0 + r) * N_ + k0 + col0;
                unsigned char b0 = bp[0], b1 = bp[1];
                att_s[r * ATT_LD + k0 + col0] =
                    acc[nt][half * 2] * 0.125f + emb[(int)b0 * H_ + h];
                att_s[r * ATT_LD + k0 + col0 + 1] =
                    acc[nt][half * 2 + 1] * 0.125f + emb[(int)b1 * H_ + h];
            }
        }
        __syncthreads();
    }

    // prefetch first V tile (buf 0 free) while softmax runs
    LOAD_KV(vbase, 0, 0);

    // ---- softmax: each warp handles 4 rows; write att to gmem + tf32 to smem ----
    {
        #pragma unroll
        for (int rr = 0; rr < 4; rr++) {
            int r = w * 4 + rr;
            float* rp = att_s + r * ATT_LD;
            float vals[16];
            float m = -1e30f;
            #pragma unroll
            for (int i = 0; i < 16; i++) { vals[i] = rp[lane + 32 * i]; m = fmaxf(m, vals[i]); }
            #pragma unroll
            for (int off = 16; off; off >>= 1) m = fmaxf(m, __shfl_xor_sync(0xffffffffu, m, off));
            float s = 0.0f;
            #pragma unroll
            for (int i = 0; i < 16; i++) { vals[i] = __expf(vals[i] - m); s += vals[i]; }
            #pragma unroll
            for (int off = 16; off; off >>= 1) s += __shfl_xor_sync(0xffffffffu, s, off);
            float inv = 1.0f / s;
            float* go = att + ((size_t)bh * N_ + q0 + r) * N_;
            #pragma unroll
            for (int i = 0; i < 16; i++) {
                float o = vals[i] * inv;
                go[lane + 32 * i] = o;
                rp[lane + 32 * i] = to_tf32(o);
            }
        }
    }
    __syncthreads();

    // ---- AV: ctx[32 x 64] = att_s[32 x 512] @ V[512 x 64] ----
    float acc2[2][4];
    #pragma unroll
    for (int nt = 0; nt < 2; nt++)
        #pragma unroll
        for (int i = 0; i < 4; i++) acc2[nt][i] = 0.0f;

    for (int jt = 0; jt < 8; jt++) {
        int j0 = jt * 64;
        if (jt + 1 < 8) {
            LOAD_KV(vbase, j0 + 64, (jt + 1) & 1);
        } else {
            asm volatile("cp.async.commit_group;\n");
        }
        asm volatile("cp.async.wait_group 1;\n");
        __syncthreads();
        float* vb_s = kv_s + (jt & 1) * 4352;
        #pragma unroll
        for (int st = 0; st < 8; st++) {
            int arow = wm * 16 + g;
            int ac = j0 + st * 8 + tig;
            uint32_t a[4];
            a[0] = __float_as_uint(att_s[arow * ATT_LD + ac]);
            a[1] = __float_as_uint(att_s[(arow + 8) * ATT_LD + ac]);
            a[2] = __float_as_uint(att_s[arow * ATT_LD + ac + 4]);
            a[3] = __float_as_uint(att_s[(arow + 8) * ATT_LD + ac + 4]);
            int krow = st * 8 + tig;
            #pragma unroll
            for (int nt = 0; nt < 2; nt++) {
                int nc = wn * 16 + nt * 8 + g;
                uint32_t bb[2];
                bb[0] = __float_as_uint(vb_s[krow * 68 + nc]);
                bb[1] = __float_as_uint(vb_s[(krow + 4) * 68 + nc]);
                mma8(acc2[nt], a, bb);
            }
        }
        __syncthreads();
    }

    // write ctx (tf32-rounded: feeds out-proj tf32 GEMM)
    {
        int row0 = wm * 16 + g;
        #pragma unroll
        for (int nt = 0; nt < 2; nt++) {
            int col0 = wn * 16 + nt * 8 + 2 * tig;
            #pragma unroll
            for (int half = 0; half < 2; half++) {
                int r = q0 + row0 + half * 8;
                float2 t;
                t.x = to_tf32(acc2[nt][half * 2]);
                t.y = to_tf32(acc2[nt][half * 2 + 1]);
                *(float2*)(ctx + ((size_t)(b * N_ + r)) * D_ + h * DK_ + col0) = t;
            }
        }
    }
}

// ---------------- launcher ---------------------------------------------------
extern "C" void kernel_launch(void* const* d_in, const int* in_sizes, int n_in,
                              void* d_out, int out_size) {
    const float* features    = (const float*)d_in[0];
    const float* boxes       = (const float*)d_in[1];
    const int*   image_sizes = (const int*)  d_in[2];
    const float* Wq = (const float*)d_in[3];
    const float* bq = (const float*)d_in[4];
    const float* Wk = (const float*)d_in[5];
    const float* bk = (const float*)d_in[6];
    const float* Wv = (const float*)d_in[7];
    const float* bv = (const float*)d_in[8];
    const float* Wo = (const float*)d_in[9];
    const float* bo = (const float*)d_in[10];
    const float* gamma = (const float*)d_in[11];
    const float* beta  = (const float*)d_in[12];
    const float* dist  = (const float*)d_in[13];

    float* out = (float*)d_out;
    float* att = out + OUT_OFF;

    void *p0 = 0, *p1 = 0, *p4 = 0, *p7 = 0, *p8 = 0;
    cudaGetSymbolAddress(&p0, g_x);
    cudaGetSymbolAddress(&p1, g_qkv);
    cudaGetSymbolAddress(&p4, g_ctx);
    cudaGetSymbolAddress(&p7, g_wc);
    cudaGetSymbolAddress(&p8, g_bc);
    float* xx   = (float*)p0;
    float* qkv  = (float*)p1;
    float* ctx  = (float*)p4;
    float* wc   = (float*)p7;
    float* bc   = (float*)p8;

    cudaFuncSetAttribute(gemm_tc, cudaFuncAttributeMaxDynamicSharedMemorySize, GEMM_SMEM);
    cudaFuncSetAttribute(attn_fused, cudaFuncAttributeMaxDynamicSharedMemorySize, ATT_SMEM);

    ln_kernel<<<ROWS, 256>>>(features, gamma, beta);
    patch_kernel<<<(ROWS + 255) / 256, 256>>>(boxes, image_sizes);
    bins_kernel<<<ROWS, 512>>>();
    cvt_w<<<WSZ / 256, 256>>>(Wq, Wk, Wv, Wo, bq, bk, bv);

    // fused QKV projection: C[8192, 2304]
    dim3 qkv_grid(QKVW / 128, ROWS / 128);   // (18, 64)
    gemm_tc<<<qkv_grid, 256, GEMM_SMEM>>>(xx, wc, bc, qkv, QKVW, 1);

    dim3 agrid(N_ / 32, B_ * H_);            // (16, 192)
    attn_fused<<<agrid, 256, ATT_SMEM>>>(qkv, dist, att, ctx);

    dim3 ogrid(D_ / 128, ROWS / 128);        // (6, 64)
    gemm_tc<<<ogrid, 256, GEMM_SMEM>>>(ctx, wc + 3 * WSZ, bo, out, D_, 0);
}